// round 9
// baseline (speedup 1.0000x reference)
#include <cuda_runtime.h>
#include <cuda_fp16.h>

#define N_ATOMS 50000
#define N_PAIRS 800000
#define FDIM    128
#define F3      384

// ---------------- scratch (device globals; no runtime allocation) ----------
__device__ int    g_count [N_ATOMS];
__device__ int    g_cursor[N_ATOMS];
__device__ int    g_offset[N_ATOMS + 1];
__device__ int    g_pairidx[N_PAIRS];
__device__ int    g_owner  [N_PAIRS];
__device__ float  g_h  [(size_t)N_ATOMS * FDIM];  // 25.6 MB
__device__ __half g_xh [(size_t)N_ATOMS * F3];    // 38.4 MB (x in fp16)
__device__ __half g_muh[(size_t)N_ATOMS * F3];    // 38.4 MB (mu in fp16)

// ---------------- small float4 helpers -------------------------------------
__device__ __forceinline__ float4 f4add(float4 a, float4 b) {
    return make_float4(a.x + b.x, a.y + b.y, a.z + b.z, a.w + b.w);
}
__device__ __forceinline__ float4 f4mul(float4 a, float4 b) {
    return make_float4(a.x * b.x, a.y * b.y, a.z * b.z, a.w * b.w);
}
__device__ __forceinline__ float4 f4fma(float4 a, float4 b, float4 c) {
    return make_float4(fmaf(a.x, b.x, c.x), fmaf(a.y, b.y, c.y),
                       fmaf(a.z, b.z, c.z), fmaf(a.w, b.w, c.w));
}
__device__ __forceinline__ float4 f4fmas(float4 a, float s, float4 c) {
    return make_float4(fmaf(a.x, s, c.x), fmaf(a.y, s, c.y),
                       fmaf(a.z, s, c.z), fmaf(a.w, s, c.w));
}
__device__ __forceinline__ float4 h4tof4(uint2 u) {
    __half2 a = *reinterpret_cast<__half2*>(&u.x);
    __half2 b = *reinterpret_cast<__half2*>(&u.y);
    float2 fa = __half22float2(a), fb = __half22float2(b);
    return make_float4(fa.x, fa.y, fb.x, fb.y);
}

// ---------------- cp.async helpers ------------------------------------------
__device__ __forceinline__ unsigned smem_u32(const void* p) {
    return (unsigned)__cvta_generic_to_shared(p);
}
__device__ __forceinline__ void cp16(unsigned d, const void* s) {
    asm volatile("cp.async.cg.shared.global [%0], [%1], 16;" :: "r"(d), "l"(s));
}
__device__ __forceinline__ void cp_commit() {
    asm volatile("cp.async.commit_group;");
}
template<int N> __device__ __forceinline__ void cp_wait() {
    asm volatile("cp.async.wait_group %0;" :: "n"(N));
}

// ---------------- CSR build -------------------------------------------------
__global__ void k_zero() {
    int i = blockIdx.x * blockDim.x + threadIdx.x;
    if (i < N_ATOMS) { g_count[i] = 0; g_cursor[i] = 0; }
}

__global__ void k_hist(const int* __restrict__ idx_i) {
    int p = blockIdx.x * blockDim.x + threadIdx.x;
    if (p < N_PAIRS) atomicAdd(&g_count[idx_i[p]], 1);
}

__global__ void k_scan() {
    __shared__ int warpsum[33];
    int lane = threadIdx.x & 31, wid = threadIdx.x >> 5;
    int running = 0;
    for (int base = 0; base < N_ATOMS; base += 1024) {
        int idx = base + (int)threadIdx.x;
        int v = (idx < N_ATOMS) ? g_count[idx] : 0;
        int incl = v;
        #pragma unroll
        for (int off = 1; off < 32; off <<= 1) {
            int t = __shfl_up_sync(0xffffffff, incl, off);
            if (lane >= off) incl += t;
        }
        if (lane == 31) warpsum[wid] = incl;
        __syncthreads();
        if (wid == 0) {
            int s = warpsum[lane];
            int si = s;
            #pragma unroll
            for (int off = 1; off < 32; off <<= 1) {
                int t = __shfl_up_sync(0xffffffff, si, off);
                if (lane >= off) si += t;
            }
            warpsum[lane] = si - s;
            if (lane == 31) warpsum[32] = si;
        }
        __syncthreads();
        if (idx < N_ATOMS) g_offset[idx] = running + warpsum[wid] + incl - v;
        running += warpsum[32];
        __syncthreads();
    }
    if (threadIdx.x == 0) g_offset[N_ATOMS] = running;
}

__global__ void k_scatter(const int* __restrict__ idx_i) {
    int p = blockIdx.x * blockDim.x + threadIdx.x;
    if (p < N_PAIRS) {
        int i = idx_i[p];
        int pos = atomicAdd(&g_cursor[i], 1);
        int dst = g_offset[i] + pos;
        g_pairidx[dst] = p;
        g_owner[dst]   = i;
    }
}

// ---------------- mu -> fp16 mirror ----------------------------------------
__global__ void k_cvt_mu(const float* __restrict__ mu) {
    size_t i = (size_t)blockIdx.x * blockDim.x + threadIdx.x;
    size_t n4 = (size_t)N_ATOMS * F3 / 4;
    if (i >= n4) return;
    float4 v = reinterpret_cast<const float4*>(mu)[i];
    __half2 h0 = __floats2half2_rn(v.x, v.y);
    __half2 h1 = __floats2half2_rn(v.z, v.w);
    uint2 u;
    u.x = *reinterpret_cast<unsigned*>(&h0);
    u.y = *reinterpret_cast<unsigned*>(&h1);
    reinterpret_cast<uint2*>(g_muh)[i] = u;
}

// ---------------- out init: out = [q ; mu] ---------------------------------
__global__ void k_init(const float* __restrict__ q, const float* __restrict__ mu,
                       float* __restrict__ out) {
    size_t i = (size_t)blockIdx.x * blockDim.x + threadIdx.x;   // float4 index
    size_t q4 = (size_t)N_ATOMS * FDIM / 4;                     // 1.6M
    size_t n4 = (size_t)N_ATOMS * (FDIM + F3) / 4;              // 6.4M
    if (i >= n4) return;
    float4 v = (i < q4) ? reinterpret_cast<const float4*>(q)[i]
                        : reinterpret_cast<const float4*>(mu)[i - q4];
    reinterpret_cast<float4*>(out)[i] = v;
}

// ---------------- 2xTF32 tensor-core GEMM ----------------------------------
__device__ __forceinline__ unsigned cvt_tf32(float x) {
    unsigned r; asm("cvt.rna.tf32.f32 %0, %1;" : "=r"(r) : "f"(x)); return r;
}
__device__ __forceinline__ void mma_tf32(float* d, const unsigned* a, const unsigned* b) {
    asm volatile(
        "mma.sync.aligned.m16n8k8.row.col.f32.tf32.tf32.f32 "
        "{%0,%1,%2,%3}, {%4,%5,%6,%7}, {%8,%9}, {%0,%1,%2,%3};"
        : "+f"(d[0]), "+f"(d[1]), "+f"(d[2]), "+f"(d[3])
        : "r"(a[0]), "r"(a[1]), "r"(a[2]), "r"(a[3]), "r"(b[0]), "r"(b[1]));
}

#define GBM 128
#define GBN 64
#define GBK 16
#define SROW 20

template<bool OUT_HALF, bool DO_SILU>
__global__ __launch_bounds__(256)
void gemm_tc(const float* __restrict__ A, const float* __restrict__ W,
             const float* __restrict__ bias, void* __restrict__ outv,
             int M, int N) {
    __shared__ float As[GBM * SROW];
    __shared__ float Ws[GBN * SROW];

    int tid  = threadIdx.x;
    int warp = tid >> 5, lane = tid & 31;
    int g = lane >> 2, t4 = lane & 3;
    int wm = warp >> 1, wn = warp & 1;
    int bm = blockIdx.y * GBM, bn = blockIdx.x * GBN;

    float acc[2][4][4];
    #pragma unroll
    for (int i = 0; i < 2; i++)
        #pragma unroll
        for (int j = 0; j < 4; j++)
            #pragma unroll
            for (int k = 0; k < 4; k++) acc[i][j][k] = 0.f;

    for (int k0 = 0; k0 < 128; k0 += GBK) {
        #pragma unroll
        for (int r = 0; r < 2; r++) {
            int t  = tid + r * 256;
            int ml = t >> 2, kq = (t & 3) * 4;
            int m = bm + ml;
            float4 v = make_float4(0, 0, 0, 0);
            if (m < M) v = *reinterpret_cast<const float4*>(A + (size_t)m * 128 + k0 + kq);
            *reinterpret_cast<float4*>(As + ml * SROW + kq) = v;
        }
        {
            int nl = tid >> 2, kq = (tid & 3) * 4;
            float4 v = *reinterpret_cast<const float4*>(W + (size_t)(bn + nl) * 128 + k0 + kq);
            *reinterpret_cast<float4*>(Ws + nl * SROW + kq) = v;
        }
        __syncthreads();

        #pragma unroll
        for (int ks = 0; ks < 2; ks++) {
            int kb = ks * 8;
            unsigned ah[2][4], al[2][4], bh[4][2];
            #pragma unroll
            for (int tm = 0; tm < 2; tm++) {
                int mb = wm * 32 + tm * 16;
                float f0 = As[(mb + g)     * SROW + kb + t4];
                float f1 = As[(mb + 8 + g) * SROW + kb + t4];
                float f2 = As[(mb + g)     * SROW + kb + t4 + 4];
                float f3 = As[(mb + 8 + g) * SROW + kb + t4 + 4];
                ah[tm][0] = cvt_tf32(f0); al[tm][0] = cvt_tf32(f0 - __uint_as_float(ah[tm][0]));
                ah[tm][1] = cvt_tf32(f1); al[tm][1] = cvt_tf32(f1 - __uint_as_float(ah[tm][1]));
                ah[tm][2] = cvt_tf32(f2); al[tm][2] = cvt_tf32(f2 - __uint_as_float(ah[tm][2]));
                ah[tm][3] = cvt_tf32(f3); al[tm][3] = cvt_tf32(f3 - __uint_as_float(ah[tm][3]));
            }
            #pragma unroll
            for (int tn = 0; tn < 4; tn++) {
                int nb = wn * 32 + tn * 8;
                bh[tn][0] = cvt_tf32(Ws[(nb + g) * SROW + kb + t4]);
                bh[tn][1] = cvt_tf32(Ws[(nb + g) * SROW + kb + t4 + 4]);
            }
            #pragma unroll
            for (int tm = 0; tm < 2; tm++)
                #pragma unroll
                for (int tn = 0; tn < 4; tn++) {
                    mma_tf32(acc[tm][tn], ah[tm], bh[tn]);
                    mma_tf32(acc[tm][tn], al[tm], bh[tn]);
                }
        }
        __syncthreads();
    }

    #pragma unroll
    for (int tm = 0; tm < 2; tm++) {
        #pragma unroll
        for (int tn = 0; tn < 4; tn++) {
            int row0 = bm + wm * 32 + tm * 16 + g;
            int col  = bn + wn * 32 + tn * 8 + t4 * 2;
            float b0 = __ldg(bias + col), b1 = __ldg(bias + col + 1);
            float v0 = acc[tm][tn][0] + b0;
            float v1 = acc[tm][tn][1] + b1;
            float v2 = acc[tm][tn][2] + b0;
            float v3 = acc[tm][tn][3] + b1;
            if (DO_SILU) {
                v0 = v0 / (1.0f + __expf(-v0));
                v1 = v1 / (1.0f + __expf(-v1));
                v2 = v2 / (1.0f + __expf(-v2));
                v3 = v3 / (1.0f + __expf(-v3));
            }
            if (OUT_HALF) {
                __half* outh = (__half*)outv;
                __half2 h01 = __floats2half2_rn(v0, v1);
                __half2 h23 = __floats2half2_rn(v2, v3);
                if (row0 < M)
                    *reinterpret_cast<__half2*>(outh + (size_t)row0 * N + col) = h01;
                if (row0 + 8 < M)
                    *reinterpret_cast<__half2*>(outh + (size_t)(row0 + 8) * N + col) = h23;
            } else {
                float* outf = (float*)outv;
                if (row0 < M)
                    *reinterpret_cast<float2*>(outf + (size_t)row0 * N + col) = make_float2(v0, v1);
                if (row0 + 8 < M)
                    *reinterpret_cast<float2*>(outf + (size_t)(row0 + 8) * N + col) = make_float2(v2, v3);
            }
        }
    }
}

// ---------------- aggregation: segmented reduction over uniform chunks ------
// Each warp owns a fixed CHUNK=128-pair slice of the CSR-ordered pair stream.
// Wij -> cp.async ring (depth 4, runs continuously across segment boundaries),
// x/mu/dir -> register ping-pong depth 2. Flush on owner change:
// interior atoms direct-store q/mu+acc; boundary atoms atomicAdd onto
// pre-initialized out.
#define WDEPTH 4
#define CHUNK  128

// smem per block (4 warps):
//   sw : 4 * WDEPTH*96 float4 = 24576 B
//   sp : 4 * CHUNK int        =  2048 B
//   sj : 4 * CHUNK int        =  2048 B
//   so : 4 * CHUNK int        =  2048 B
#define AGG_SMEM (24576 + 3 * 2048)

struct XM {
    uint2 x0, x1, x2, m0, m1, m2;
    float d0, d1, d2;
};

__global__ __launch_bounds__(128)
void k_agg(const float* __restrict__ q, const float* __restrict__ mu,
           const float* __restrict__ Wij, const float* __restrict__ dir,
           const int* __restrict__ idxj, float* __restrict__ out) {
    extern __shared__ char dsm[];
    int warp = threadIdx.x >> 5;
    int lane = threadIdx.x & 31;

    float4* sw = reinterpret_cast<float4*>(dsm)                 + warp * (WDEPTH * 96);
    int*    sp = reinterpret_cast<int*>(dsm + 24576)            + warp * CHUNK;
    int*    sj = reinterpret_cast<int*>(dsm + 24576 + 2048)     + warp * CHUNK;
    int*    so = reinterpret_cast<int*>(dsm + 24576 + 4096)     + warp * CHUNK;

    int chunk = blockIdx.x * 4 + warp;
    int c0 = chunk * CHUNK;
    if (c0 >= N_PAIRS) return;
    int c1 = c0 + CHUNK; if (c1 > N_PAIRS) c1 = N_PAIRS;
    int cn = c1 - c0;

    // stage pair indices, gathered j, owners (coalesced where possible)
    for (int k = lane; k < cn; k += 32) {
        int p = __ldg(g_pairidx + c0 + k);
        sp[k] = p;
        sj[k] = __ldg(idxj + p);
        so[k] = __ldg(g_owner + c0 + k);
    }
    __syncwarp();

    float4 aq = make_float4(0, 0, 0, 0);
    float4 a0 = aq, a1 = aq, a2 = aq;

    auto issue_w = [&](int k) {
        if (k < cn) {
            int p = sp[k];
            int slot = k & (WDEPTH - 1);
            const char* wsrc = (const char*)Wij + (size_t)p * 1536 + lane * 16;
            unsigned wdst = smem_u32(sw + slot * 96 + lane);
            cp16(wdst,        wsrc);
            cp16(wdst + 512,  wsrc + 512);
            cp16(wdst + 1024, wsrc + 1024);
        }
        cp_commit();
    };

    auto load_xm = [&](XM& R, int k) {
        int p = sp[k], j = sj[k];
        R.d0 = __ldg(dir + (size_t)p * 3 + 0);
        R.d1 = __ldg(dir + (size_t)p * 3 + 1);
        R.d2 = __ldg(dir + (size_t)p * 3 + 2);
        const uint2* xp = reinterpret_cast<const uint2*>(g_xh)  + (size_t)j * 96;
        const uint2* mp = reinterpret_cast<const uint2*>(g_muh) + (size_t)j * 96;
        R.x0 = xp[lane]; R.x1 = xp[lane + 32]; R.x2 = xp[lane + 64];
        R.m0 = mp[lane]; R.m1 = mp[lane + 32]; R.m2 = mp[lane + 64];
    };

    auto accum = [&](const XM& R, int slot) {
        float4 w0 = sw[slot * 96 + lane];
        float4 w1 = sw[slot * 96 + lane + 32];
        float4 w2 = sw[slot * 96 + lane + 64];
        float4 x0 = h4tof4(R.x0), x1 = h4tof4(R.x1), x2 = h4tof4(R.x2);
        float4 m0 = h4tof4(R.m0), m1 = h4tof4(R.m1), m2 = h4tof4(R.m2);
        aq = f4fma(w0, x0, aq);
        float4 Rv = f4mul(w1, x1);
        float4 MM = f4mul(w2, x2);
        a0 = f4fma(MM, m0, f4fmas(Rv, R.d0, a0));
        a1 = f4fma(MM, m1, f4fmas(Rv, R.d1, a1));
        a2 = f4fma(MM, m2, f4fmas(Rv, R.d2, a2));
    };

    auto flush = [&](int i) {
        int sOff = __ldg(g_offset + i), eOff = __ldg(g_offset + i + 1);
        if (sOff >= c0 && eOff <= c1) {
            // interior: this warp saw the whole segment -> direct store
            const float4* qp = reinterpret_cast<const float4*>(q) + (size_t)i * 32;
            float4* oq = reinterpret_cast<float4*>(out) + (size_t)i * 32;
            oq[lane] = f4add(qp[lane], aq);
            const float4* mup = reinterpret_cast<const float4*>(mu) + (size_t)i * 96;
            float4* om = reinterpret_cast<float4*>(out + (size_t)N_ATOMS * FDIM) + (size_t)i * 96;
            om[lane]      = f4add(mup[lane],      a0);
            om[lane + 32] = f4add(mup[lane + 32], a1);
            om[lane + 64] = f4add(mup[lane + 64], a2);
        } else {
            // boundary: partial sum -> atomicAdd onto pre-initialized out
            float* oqf = out + (size_t)i * FDIM + lane * 4;
            atomicAdd(oqf + 0, aq.x); atomicAdd(oqf + 1, aq.y);
            atomicAdd(oqf + 2, aq.z); atomicAdd(oqf + 3, aq.w);
            float* omf = out + (size_t)N_ATOMS * FDIM + (size_t)i * F3;
            float* r0 = omf + lane * 4;
            float* r1 = omf + 128 + lane * 4;
            float* r2 = omf + 256 + lane * 4;
            atomicAdd(r0 + 0, a0.x); atomicAdd(r0 + 1, a0.y);
            atomicAdd(r0 + 2, a0.z); atomicAdd(r0 + 3, a0.w);
            atomicAdd(r1 + 0, a1.x); atomicAdd(r1 + 1, a1.y);
            atomicAdd(r1 + 2, a1.z); atomicAdd(r1 + 3, a1.w);
            atomicAdd(r2 + 0, a2.x); atomicAdd(r2 + 1, a2.y);
            atomicAdd(r2 + 2, a2.z); atomicAdd(r2 + 3, a2.w);
        }
        aq = make_float4(0, 0, 0, 0);
        a0 = aq; a1 = aq; a2 = aq;
    };

    XM A, B;
    issue_w(0); issue_w(1); issue_w(2);
    load_xm(A, 0);

    for (int k = 0; k < cn; ) {
        issue_w(k + 3);
        if (k + 1 < cn) load_xm(B, k + 1);
        cp_wait<WDEPTH - 1>();
        accum(A, k & (WDEPTH - 1));
        if (k + 1 == cn || so[k + 1] != so[k]) flush(so[k]);
        ++k;
        if (k >= cn) break;

        issue_w(k + 3);
        if (k + 1 < cn) load_xm(A, k + 1);
        cp_wait<WDEPTH - 1>();
        accum(B, k & (WDEPTH - 1));
        if (k + 1 == cn || so[k + 1] != so[k]) flush(so[k]);
        ++k;
    }
}

// ---------------- launch ----------------------------------------------------
static cudaStream_t s_side = nullptr;
static cudaEvent_t  s_evFork = nullptr, s_evJoin = nullptr;

extern "C" void kernel_launch(void* const* d_in, const int* in_sizes, int n_in,
                              void* d_out, int out_size) {
    const float* q   = (const float*)d_in[0];
    const float* mu  = (const float*)d_in[1];
    const float* Wij = (const float*)d_in[2];
    const float* dir = (const float*)d_in[3];
    const int*   pl  = (const int*)d_in[4];
    const float* W1  = (const float*)d_in[5];
    const float* b1  = (const float*)d_in[6];
    const float* W2  = (const float*)d_in[7];
    const float* b2  = (const float*)d_in[8];
    float* out = (float*)d_out;

    const int* idx_i = pl;
    const int* idx_j = pl + N_PAIRS;

    float  *hbuf = nullptr;
    __half *xh   = nullptr;
    cudaGetSymbolAddress((void**)&hbuf, g_h);
    cudaGetSymbolAddress((void**)&xh,   g_xh);

    if (!s_side) {
        cudaStreamCreateWithFlags(&s_side, cudaStreamNonBlocking);
        cudaEventCreateWithFlags(&s_evFork, cudaEventDisableTiming);
        cudaEventCreateWithFlags(&s_evJoin, cudaEventDisableTiming);
        cudaFuncSetAttribute(k_agg, cudaFuncAttributeMaxDynamicSharedMemorySize, AGG_SMEM);
    }

    // fork: CSR chain + mu conversion + out init on side stream
    cudaEventRecord(s_evFork, 0);
    cudaStreamWaitEvent(s_side, s_evFork, 0);

    k_zero   <<<(N_ATOMS + 255) / 256, 256, 0, s_side>>>();
    k_hist   <<<(N_PAIRS + 255) / 256, 256, 0, s_side>>>(idx_i);
    k_scan   <<<1, 1024, 0, s_side>>>();
    k_scatter<<<(N_PAIRS + 255) / 256, 256, 0, s_side>>>(idx_i);
    {
        size_t n4 = (size_t)N_ATOMS * F3 / 4;
        k_cvt_mu<<<(unsigned)((n4 + 255) / 256), 256, 0, s_side>>>(mu);
    }
    {
        size_t n4 = (size_t)N_ATOMS * (FDIM + F3) / 4;
        k_init<<<(unsigned)((n4 + 255) / 256), 256, 0, s_side>>>(q, mu, out);
    }
    cudaEventRecord(s_evJoin, s_side);

    // main: GEMM chain
    dim3 g1(FDIM / GBN, (N_ATOMS + GBM - 1) / GBM);
    gemm_tc<false, true><<<g1, 256>>>(q, W1, b1, hbuf, N_ATOMS, FDIM);
    dim3 g2(F3 / GBN, (N_ATOMS + GBM - 1) / GBM);
    gemm_tc<true, false><<<g2, 256>>>(hbuf, W2, b2, xh, N_ATOMS, F3);

    // join, then segmented aggregation
    cudaStreamWaitEvent(0, s_evJoin, 0);
    {
        int nchunks = (N_PAIRS + CHUNK - 1) / CHUNK;
        int nblocks = (nchunks + 3) / 4;
        k_agg<<<nblocks, 128, AGG_SMEM>>>(q, mu, Wij, dir, idx_j, out);
    }
}

// round 11
// speedup vs baseline: 1.1954x; 1.1954x over previous
#include <cuda_runtime.h>
#include <cuda_fp16.h>

#define N_ATOMS 50000
#define N_PAIRS 800000
#define FDIM    128
#define F3      384

// ---------------- scratch (device globals; no runtime allocation) ----------
__device__ int    g_count [N_ATOMS];
__device__ int    g_cursor[N_ATOMS];
__device__ int    g_offset[N_ATOMS + 1];
__device__ int    g_pairidx[N_PAIRS];
__device__ __half g_h  [(size_t)N_ATOMS * FDIM];  // 12.8 MB (h in fp16)
__device__ __half g_xh [(size_t)N_ATOMS * F3];    // 38.4 MB (x in fp16)
__device__ __half g_muh[(size_t)N_ATOMS * F3];    // 38.4 MB (mu in fp16)

// ---------------- small float4 helpers -------------------------------------
__device__ __forceinline__ float4 f4add(float4 a, float4 b) {
    return make_float4(a.x + b.x, a.y + b.y, a.z + b.z, a.w + b.w);
}
__device__ __forceinline__ float4 f4mul(float4 a, float4 b) {
    return make_float4(a.x * b.x, a.y * b.y, a.z * b.z, a.w * b.w);
}
__device__ __forceinline__ float4 f4fma(float4 a, float4 b, float4 c) {
    return make_float4(fmaf(a.x, b.x, c.x), fmaf(a.y, b.y, c.y),
                       fmaf(a.z, b.z, c.z), fmaf(a.w, b.w, c.w));
}
__device__ __forceinline__ float4 f4fmas(float4 a, float s, float4 c) {
    return make_float4(fmaf(a.x, s, c.x), fmaf(a.y, s, c.y),
                       fmaf(a.z, s, c.z), fmaf(a.w, s, c.w));
}
__device__ __forceinline__ float4 h4tof4(uint2 u) {
    __half2 a = *reinterpret_cast<__half2*>(&u.x);
    __half2 b = *reinterpret_cast<__half2*>(&u.y);
    float2 fa = __half22float2(a), fb = __half22float2(b);
    return make_float4(fa.x, fa.y, fb.x, fb.y);
}
__device__ __forceinline__ uint2 f4toh4(float4 v) {
    __half2 h0 = __floats2half2_rn(v.x, v.y);
    __half2 h1 = __floats2half2_rn(v.z, v.w);
    uint2 u;
    u.x = *reinterpret_cast<unsigned*>(&h0);
    u.y = *reinterpret_cast<unsigned*>(&h1);
    return u;
}

// ---------------- cp.async helpers ------------------------------------------
__device__ __forceinline__ unsigned smem_u32(const void* p) {
    return (unsigned)__cvta_generic_to_shared(p);
}
__device__ __forceinline__ void cp16(unsigned d, const void* s) {
    asm volatile("cp.async.cg.shared.global [%0], [%1], 16;" :: "r"(d), "l"(s));
}
__device__ __forceinline__ void cp_commit() {
    asm volatile("cp.async.commit_group;");
}
template<int N> __device__ __forceinline__ void cp_wait() {
    asm volatile("cp.async.wait_group %0;" :: "n"(N));
}

// ---------------- CSR build -------------------------------------------------
__global__ void k_zero() {
    int i = blockIdx.x * blockDim.x + threadIdx.x;
    if (i < N_ATOMS) { g_count[i] = 0; g_cursor[i] = 0; }
}

__global__ void k_hist(const int* __restrict__ idx_i) {
    int p = blockIdx.x * blockDim.x + threadIdx.x;
    if (p < N_PAIRS) atomicAdd(&g_count[idx_i[p]], 1);
}

__global__ void k_scan() {
    __shared__ int warpsum[33];
    int lane = threadIdx.x & 31, wid = threadIdx.x >> 5;
    int running = 0;
    for (int base = 0; base < N_ATOMS; base += 1024) {
        int idx = base + (int)threadIdx.x;
        int v = (idx < N_ATOMS) ? g_count[idx] : 0;
        int incl = v;
        #pragma unroll
        for (int off = 1; off < 32; off <<= 1) {
            int t = __shfl_up_sync(0xffffffff, incl, off);
            if (lane >= off) incl += t;
        }
        if (lane == 31) warpsum[wid] = incl;
        __syncthreads();
        if (wid == 0) {
            int s = warpsum[lane];
            int si = s;
            #pragma unroll
            for (int off = 1; off < 32; off <<= 1) {
                int t = __shfl_up_sync(0xffffffff, si, off);
                if (lane >= off) si += t;
            }
            warpsum[lane] = si - s;
            if (lane == 31) warpsum[32] = si;
        }
        __syncthreads();
        if (idx < N_ATOMS) g_offset[idx] = running + warpsum[wid] + incl - v;
        running += warpsum[32];
        __syncthreads();
    }
    if (threadIdx.x == 0) g_offset[N_ATOMS] = running;
}

__global__ void k_scatter(const int* __restrict__ idx_i) {
    int p = blockIdx.x * blockDim.x + threadIdx.x;
    if (p < N_PAIRS) {
        int i = idx_i[p];
        int pos = atomicAdd(&g_cursor[i], 1);
        g_pairidx[g_offset[i] + pos] = p;
    }
}

// ---------------- mu -> fp16 mirror ----------------------------------------
__global__ void k_cvt_mu(const float* __restrict__ mu) {
    size_t i = (size_t)blockIdx.x * blockDim.x + threadIdx.x;
    size_t n4 = (size_t)N_ATOMS * F3 / 4;
    if (i >= n4) return;
    reinterpret_cast<uint2*>(g_muh)[i] = f4toh4(reinterpret_cast<const float4*>(mu)[i]);
}

// ---------------- fp16 tensor-core GEMM (m16n8k16, fp32 accum) -------------
// out[m,n] = sum_k A[m,k]*W[n,k] + b[n], K=128 fixed.
// Block 256 thr (8 warps 4x2), BM=128, BN=64; K staged in 2 chunks of 64.
__device__ __forceinline__ void mma_f16(float* d, const unsigned* a, const unsigned* b) {
    asm volatile(
        "mma.sync.aligned.m16n8k16.row.col.f32.f16.f16.f32 "
        "{%0,%1,%2,%3}, {%4,%5,%6,%7}, {%8,%9}, {%0,%1,%2,%3};"
        : "+f"(d[0]), "+f"(d[1]), "+f"(d[2]), "+f"(d[3])
        : "r"(a[0]), "r"(a[1]), "r"(a[2]), "r"(a[3]), "r"(b[0]), "r"(b[1]));
}

#define GBM 128
#define GBN 64
#define HSTRIDE 36   // uints per row (32 data + 4 pad)

template<bool IN_HALF, bool DO_SILU>
__global__ __launch_bounds__(256)
void gemm_tc(const void* __restrict__ Av, const float* __restrict__ W,
             const float* __restrict__ bias, __half* __restrict__ outh,
             int M, int N) {
    __shared__ unsigned As_h[GBM * HSTRIDE];   // 18432 B
    __shared__ unsigned Ws_h[GBN * HSTRIDE];   //  9216 B

    int tid  = threadIdx.x;
    int warp = tid >> 5, lane = tid & 31;
    int g = lane >> 2, t4 = lane & 3;
    int wm = warp >> 1, wn = warp & 1;
    int bm = blockIdx.y * GBM, bn = blockIdx.x * GBN;

    float acc[2][4][4];
    #pragma unroll
    for (int i = 0; i < 2; i++)
        #pragma unroll
        for (int j = 0; j < 4; j++)
            #pragma unroll
            for (int k = 0; k < 4; k++) acc[i][j][k] = 0.f;

    #pragma unroll
    for (int k0 = 0; k0 < 128; k0 += 64) {
        // stage A chunk (128 rows x 64 cols = 16 uint2 per row)
        if (IN_HALF) {
            const uint2* A_h = reinterpret_cast<const uint2*>(Av);  // row = 32 uint2
            #pragma unroll
            for (int r = 0; r < 8; r++) {
                int t  = tid + r * 256;
                int ml = t >> 4, c = t & 15;          // c: uint2 within chunk (16 per row)
                uint2 v = make_uint2(0, 0);
                if (bm + ml < M) v = A_h[(size_t)(bm + ml) * 32 + k0 / 4 + c];
                *reinterpret_cast<uint2*>(As_h + ml * HSTRIDE + c * 2) = v;
            }
        } else {
            const float* A = reinterpret_cast<const float*>(Av);
            #pragma unroll
            for (int r = 0; r < 8; r++) {
                int t  = tid + r * 256;
                int ml = t >> 4, c = t & 15;          // c: float4 within chunk (16 per row)
                float4 v = make_float4(0, 0, 0, 0);
                if (bm + ml < M) v = *reinterpret_cast<const float4*>(A + (size_t)(bm + ml) * 128 + k0 + c * 4);
                *reinterpret_cast<uint2*>(As_h + ml * HSTRIDE + c * 2) = f4toh4(v);
            }
        }
        // stage W chunk (64 rows x 64 cols), fp32 -> fp16
        #pragma unroll
        for (int r = 0; r < 4; r++) {
            int t  = tid + r * 256;
            int nl = t >> 4, c = t & 15;
            float4 v = *reinterpret_cast<const float4*>(W + (size_t)(bn + nl) * 128 + k0 + c * 4);
            *reinterpret_cast<uint2*>(Ws_h + nl * HSTRIDE + c * 2) = f4toh4(v);
        }
        __syncthreads();

        #pragma unroll
        for (int ks = 0; ks < 4; ks++) {          // 4 x k16 = 64
            int ku = ks * 8;                      // uint offset within row
            unsigned a[2][4], b[4][2];
            #pragma unroll
            for (int tm = 0; tm < 2; tm++) {
                int mb = wm * 32 + tm * 16;
                const unsigned* r0 = As_h + (mb + g) * HSTRIDE + ku;
                const unsigned* r1 = As_h + (mb + 8 + g) * HSTRIDE + ku;
                a[tm][0] = r0[t4];     a[tm][1] = r1[t4];
                a[tm][2] = r0[t4 + 4]; a[tm][3] = r1[t4 + 4];
            }
            #pragma unroll
            for (int tn = 0; tn < 4; tn++) {
                int nb = wn * 32 + tn * 8;
                const unsigned* rw = Ws_h + (nb + g) * HSTRIDE + ku;
                b[tn][0] = rw[t4]; b[tn][1] = rw[t4 + 4];
            }
            #pragma unroll
            for (int tm = 0; tm < 2; tm++)
                #pragma unroll
                for (int tn = 0; tn < 4; tn++)
                    mma_f16(acc[tm][tn], a[tm], b[tn]);
        }
        __syncthreads();
    }

    #pragma unroll
    for (int tm = 0; tm < 2; tm++) {
        #pragma unroll
        for (int tn = 0; tn < 4; tn++) {
            int row0 = bm + wm * 32 + tm * 16 + g;
            int col  = bn + wn * 32 + tn * 8 + t4 * 2;
            float b0 = __ldg(bias + col), b1 = __ldg(bias + col + 1);
            float v0 = acc[tm][tn][0] + b0;
            float v1 = acc[tm][tn][1] + b1;
            float v2 = acc[tm][tn][2] + b0;
            float v3 = acc[tm][tn][3] + b1;
            if (DO_SILU) {
                v0 = v0 / (1.0f + __expf(-v0));
                v1 = v1 / (1.0f + __expf(-v1));
                v2 = v2 / (1.0f + __expf(-v2));
                v3 = v3 / (1.0f + __expf(-v3));
            }
            __half2 h01 = __floats2half2_rn(v0, v1);
            __half2 h23 = __floats2half2_rn(v2, v3);
            if (row0 < M)
                *reinterpret_cast<__half2*>(outh + (size_t)row0 * N + col) = h01;
            if (row0 + 8 < M)
                *reinterpret_cast<__half2*>(outh + (size_t)(row0 + 8) * N + col) = h23;
        }
    }
}

// ---------------- aggregation: asymmetric pipeline (R8, proven) -------------
// Wij (always DRAM) -> cp.async ring depth 4 in smem.
// x/mu (mostly L2)  -> register ping-pong depth 2.
#define WDEPTH 4
#define MAXSEG 64
#define AGG_SMEM (24576 + 1024 + 1024 + 4096)

struct XM {
    uint2 x0, x1, x2, m0, m1, m2;
    float d0, d1, d2;
};

__global__ __launch_bounds__(128)
void k_agg(const float* __restrict__ q, const float* __restrict__ mu,
           const float* __restrict__ Wij, const float* __restrict__ dir,
           const int* __restrict__ idxj, float* __restrict__ out) {
    extern __shared__ char dsm[];
    int warp = threadIdx.x >> 5;
    int lane = threadIdx.x & 31;

    float4* sw = reinterpret_cast<float4*>(dsm)              + warp * (WDEPTH * 96);
    int*    sp = reinterpret_cast<int*>(dsm + 24576)         + warp * MAXSEG;
    int*    sj = reinterpret_cast<int*>(dsm + 24576 + 1024)  + warp * MAXSEG;
    float4* sd = reinterpret_cast<float4*>(dsm + 24576 + 2048) + warp * MAXSEG;

    int i = blockIdx.x * 4 + warp;
    if (i >= N_ATOMS) return;

    int s = g_offset[i], e = g_offset[i + 1];
    int n = e - s;

    int nc = n < MAXSEG ? n : MAXSEG;
    for (int t = lane; t < nc; t += 32) {
        int p = __ldg(g_pairidx + s + t);
        sp[t] = p;
        sj[t] = __ldg(idxj + p);
        sd[t] = make_float4(__ldg(dir + (size_t)p * 3 + 0),
                            __ldg(dir + (size_t)p * 3 + 1),
                            __ldg(dir + (size_t)p * 3 + 2), 0.f);
    }
    __syncwarp();

    float4 aq = make_float4(0, 0, 0, 0);
    float4 a0 = aq, a1 = aq, a2 = aq;

    auto issue_w = [&](int t) {
        if (t < n) {
            int p = (t < MAXSEG) ? sp[t] : __ldg(g_pairidx + s + t);
            int slot = t & (WDEPTH - 1);
            const char* wsrc = (const char*)Wij + (size_t)p * 1536 + lane * 16;
            unsigned wdst = smem_u32(sw + slot * 96 + lane);
            cp16(wdst,        wsrc);
            cp16(wdst + 512,  wsrc + 512);
            cp16(wdst + 1024, wsrc + 1024);
        }
        cp_commit();
    };

    auto load_xm = [&](XM& R, int t) {
        int p, j;
        if (t < MAXSEG) {
            j = sj[t];
            float4 dv = sd[t];
            R.d0 = dv.x; R.d1 = dv.y; R.d2 = dv.z;
        } else {
            p = __ldg(g_pairidx + s + t);
            j = __ldg(idxj + p);
            R.d0 = __ldg(dir + (size_t)p * 3 + 0);
            R.d1 = __ldg(dir + (size_t)p * 3 + 1);
            R.d2 = __ldg(dir + (size_t)p * 3 + 2);
        }
        const uint2* xp = reinterpret_cast<const uint2*>(g_xh)  + (size_t)j * 96;
        const uint2* mp = reinterpret_cast<const uint2*>(g_muh) + (size_t)j * 96;
        R.x0 = xp[lane]; R.x1 = xp[lane + 32]; R.x2 = xp[lane + 64];
        R.m0 = mp[lane]; R.m1 = mp[lane + 32]; R.m2 = mp[lane + 64];
    };

    auto accum = [&](const XM& R, int slot) {
        float4 w0 = sw[slot * 96 + lane];
        float4 w1 = sw[slot * 96 + lane + 32];
        float4 w2 = sw[slot * 96 + lane + 64];
        float4 x0 = h4tof4(R.x0), x1 = h4tof4(R.x1), x2 = h4tof4(R.x2);
        float4 m0 = h4tof4(R.m0), m1 = h4tof4(R.m1), m2 = h4tof4(R.m2);
        aq = f4fma(w0, x0, aq);
        float4 Rv = f4mul(w1, x1);
        float4 MM = f4mul(w2, x2);
        a0 = f4fma(MM, m0, f4fmas(Rv, R.d0, a0));
        a1 = f4fma(MM, m1, f4fmas(Rv, R.d1, a1));
        a2 = f4fma(MM, m2, f4fmas(Rv, R.d2, a2));
    };

    XM A, B;
    issue_w(0); issue_w(1); issue_w(2);
    if (n > 0) load_xm(A, 0);

    for (int t = 0; t < n; ) {
        issue_w(t + 3);
        if (t + 1 < n) load_xm(B, t + 1);
        cp_wait<WDEPTH - 1>();
        accum(A, t & (WDEPTH - 1));
        ++t;
        if (t >= n) break;

        issue_w(t + 3);
        if (t + 1 < n) load_xm(A, t + 1);
        cp_wait<WDEPTH - 1>();
        accum(B, t & (WDEPTH - 1));
        ++t;
    }

    const float4* qp = reinterpret_cast<const float4*>(q) + (size_t)i * 32;
    float4* oq = reinterpret_cast<float4*>(out) + (size_t)i * 32;
    oq[lane] = f4add(qp[lane], aq);

    const float4* mup = reinterpret_cast<const float4*>(mu) + (size_t)i * 96;
    float4* om = reinterpret_cast<float4*>(out + (size_t)N_ATOMS * FDIM) + (size_t)i * 96;
    om[lane]      = f4add(mup[lane],      a0);
    om[lane + 32] = f4add(mup[lane + 32], a1);
    om[lane + 64] = f4add(mup[lane + 64], a2);
}

// ---------------- launch ----------------------------------------------------
static cudaStream_t s_side = nullptr;
static cudaEvent_t  s_evFork = nullptr, s_evJoin = nullptr;

extern "C" void kernel_launch(void* const* d_in, const int* in_sizes, int n_in,
                              void* d_out, int out_size) {
    const float* q   = (const float*)d_in[0];
    const float* mu  = (const float*)d_in[1];
    const float* Wij = (const float*)d_in[2];
    const float* dir = (const float*)d_in[3];
    const int*   pl  = (const int*)d_in[4];
    const float* W1  = (const float*)d_in[5];
    const float* b1  = (const float*)d_in[6];
    const float* W2  = (const float*)d_in[7];
    const float* b2  = (const float*)d_in[8];
    float* out = (float*)d_out;

    const int* idx_i = pl;
    const int* idx_j = pl + N_PAIRS;

    __half *hbuf = nullptr, *xh = nullptr;
    cudaGetSymbolAddress((void**)&hbuf, g_h);
    cudaGetSymbolAddress((void**)&xh,   g_xh);

    if (!s_side) {
        cudaStreamCreateWithFlags(&s_side, cudaStreamNonBlocking);
        cudaEventCreateWithFlags(&s_evFork, cudaEventDisableTiming);
        cudaEventCreateWithFlags(&s_evJoin, cudaEventDisableTiming);
        cudaFuncSetAttribute(k_agg, cudaFuncAttributeMaxDynamicSharedMemorySize, AGG_SMEM);
    }

    // fork: CSR chain + mu conversion on side stream, GEMM chain on main
    cudaEventRecord(s_evFork, 0);
    cudaStreamWaitEvent(s_side, s_evFork, 0);

    k_zero   <<<(N_ATOMS + 255) / 256, 256, 0, s_side>>>();
    k_hist   <<<(N_PAIRS + 255) / 256, 256, 0, s_side>>>(idx_i);
    k_scan   <<<1, 1024, 0, s_side>>>();
    k_scatter<<<(N_PAIRS + 255) / 256, 256, 0, s_side>>>(idx_i);
    {
        size_t n4 = (size_t)N_ATOMS * F3 / 4;
        k_cvt_mu<<<(unsigned)((n4 + 255) / 256), 256, 0, s_side>>>(mu);
    }
    cudaEventRecord(s_evJoin, s_side);

    // main: fp16 tensor-core GEMM chain
    dim3 g1(FDIM / GBN, (N_ATOMS + GBM - 1) / GBM);
    gemm_tc<false, true><<<g1, 256>>>(q, W1, b1, hbuf, N_ATOMS, FDIM);
    dim3 g2(F3 / GBN, (N_ATOMS + GBM - 1) / GBM);
    gemm_tc<true, false><<<g2, 256>>>(hbuf, W2, b2, xh, N_ATOMS, F3);

    // join, then aggregate
    cudaStreamWaitEvent(0, s_evJoin, 0);
    k_agg<<<(N_ATOMS + 3) / 4, 128, AGG_SMEM>>>(q, mu, Wij, dir, idx_j, out);
}

// round 13
// speedup vs baseline: 1.2808x; 1.0714x over previous
#include <cuda_runtime.h>
#include <cuda_fp16.h>

#define N_ATOMS 50000
#define N_PAIRS 800000
#define FDIM    128
#define F3      384

// ---------------- scratch (device globals; no runtime allocation) ----------
__device__ int    g_count [N_ATOMS];
__device__ int    g_cursor[N_ATOMS];
__device__ int    g_offset[N_ATOMS + 1];
__device__ int    g_pairidx[N_PAIRS];
__device__ __half g_h  [(size_t)N_ATOMS * FDIM];  // 12.8 MB (h in fp16)
__device__ __half g_xh [(size_t)N_ATOMS * F3];    // 38.4 MB (x in fp16)
__device__ __half g_muh[(size_t)N_ATOMS * F3];    // 38.4 MB (mu in fp16)

// ---------------- small float4 helpers -------------------------------------
__device__ __forceinline__ float4 f4add(float4 a, float4 b) {
    return make_float4(a.x + b.x, a.y + b.y, a.z + b.z, a.w + b.w);
}
__device__ __forceinline__ float4 f4mul(float4 a, float4 b) {
    return make_float4(a.x * b.x, a.y * b.y, a.z * b.z, a.w * b.w);
}
__device__ __forceinline__ float4 f4fma(float4 a, float4 b, float4 c) {
    return make_float4(fmaf(a.x, b.x, c.x), fmaf(a.y, b.y, c.y),
                       fmaf(a.z, b.z, c.z), fmaf(a.w, b.w, c.w));
}
__device__ __forceinline__ float4 f4fmas(float4 a, float s, float4 c) {
    return make_float4(fmaf(a.x, s, c.x), fmaf(a.y, s, c.y),
                       fmaf(a.z, s, c.z), fmaf(a.w, s, c.w));
}
__device__ __forceinline__ float4 h4tof4(uint2 u) {
    __half2 a = *reinterpret_cast<__half2*>(&u.x);
    __half2 b = *reinterpret_cast<__half2*>(&u.y);
    float2 fa = __half22float2(a), fb = __half22float2(b);
    return make_float4(fa.x, fa.y, fb.x, fb.y);
}
__device__ __forceinline__ uint2 f4toh4(float4 v) {
    __half2 h0 = __floats2half2_rn(v.x, v.y);
    __half2 h1 = __floats2half2_rn(v.z, v.w);
    uint2 u;
    u.x = *reinterpret_cast<unsigned*>(&h0);
    u.y = *reinterpret_cast<unsigned*>(&h1);
    return u;
}

// ---------------- cp.async / cache-policy helpers ---------------------------
__device__ __forceinline__ unsigned smem_u32(const void* p) {
    return (unsigned)__cvta_generic_to_shared(p);
}
__device__ __forceinline__ unsigned long long mk_evict_first() {
    unsigned long long pol;
    asm("createpolicy.fractional.L2::evict_first.b64 %0, 1.0;" : "=l"(pol));
    return pol;
}
__device__ __forceinline__ unsigned long long mk_evict_last() {
    unsigned long long pol;
    asm("createpolicy.fractional.L2::evict_last.b64 %0, 1.0;" : "=l"(pol));
    return pol;
}
__device__ __forceinline__ void cp16_ef(unsigned d, const void* s, unsigned long long pol) {
    asm volatile("cp.async.cg.shared.global.L2::cache_hint [%0], [%1], 16, %2;"
                 :: "r"(d), "l"(s), "l"(pol));
}
__device__ __forceinline__ void cp_commit() {
    asm volatile("cp.async.commit_group;");
}
template<int N> __device__ __forceinline__ void cp_wait() {
    asm volatile("cp.async.wait_group %0;" :: "n"(N));
}
// x/mu gathers: keep in L2 via cache-policy operand form (any width legal)
__device__ __forceinline__ uint2 ldg_el(const uint2* p, unsigned long long pol) {
    uint2 v;
    asm volatile("ld.global.nc.L2::cache_hint.v2.u32 {%0,%1}, [%2], %3;"
                 : "=r"(v.x), "=r"(v.y) : "l"(p), "l"(pol));
    return v;
}

// ---------------- CSR build -------------------------------------------------
__global__ void k_zero() {
    int i = blockIdx.x * blockDim.x + threadIdx.x;
    if (i < N_ATOMS) { g_count[i] = 0; g_cursor[i] = 0; }
}

__global__ void k_hist(const int* __restrict__ idx_i) {
    int p = blockIdx.x * blockDim.x + threadIdx.x;
    if (p < N_PAIRS) atomicAdd(&g_count[idx_i[p]], 1);
}

__global__ void k_scan() {
    __shared__ int warpsum[33];
    int lane = threadIdx.x & 31, wid = threadIdx.x >> 5;
    int running = 0;
    for (int base = 0; base < N_ATOMS; base += 1024) {
        int idx = base + (int)threadIdx.x;
        int v = (idx < N_ATOMS) ? g_count[idx] : 0;
        int incl = v;
        #pragma unroll
        for (int off = 1; off < 32; off <<= 1) {
            int t = __shfl_up_sync(0xffffffff, incl, off);
            if (lane >= off) incl += t;
        }
        if (lane == 31) warpsum[wid] = incl;
        __syncthreads();
        if (wid == 0) {
            int s = warpsum[lane];
            int si = s;
            #pragma unroll
            for (int off = 1; off < 32; off <<= 1) {
                int t = __shfl_up_sync(0xffffffff, si, off);
                if (lane >= off) si += t;
            }
            warpsum[lane] = si - s;
            if (lane == 31) warpsum[32] = si;
        }
        __syncthreads();
        if (idx < N_ATOMS) g_offset[idx] = running + warpsum[wid] + incl - v;
        running += warpsum[32];
        __syncthreads();
    }
    if (threadIdx.x == 0) g_offset[N_ATOMS] = running;
}

__global__ void k_scatter(const int* __restrict__ idx_i) {
    int p = blockIdx.x * blockDim.x + threadIdx.x;
    if (p < N_PAIRS) {
        int i = idx_i[p];
        int pos = atomicAdd(&g_cursor[i], 1);
        g_pairidx[g_offset[i] + pos] = p;
    }
}

// ---------------- mu -> fp16 mirror ----------------------------------------
__global__ void k_cvt_mu(const float* __restrict__ mu) {
    size_t i = (size_t)blockIdx.x * blockDim.x + threadIdx.x;
    size_t n4 = (size_t)N_ATOMS * F3 / 4;
    if (i >= n4) return;
    reinterpret_cast<uint2*>(g_muh)[i] = f4toh4(reinterpret_cast<const float4*>(mu)[i]);
}

// ---------------- fp16 tensor-core GEMM (m16n8k16, fp32 accum) -------------
__device__ __forceinline__ void mma_f16(float* d, const unsigned* a, const unsigned* b) {
    asm volatile(
        "mma.sync.aligned.m16n8k16.row.col.f32.f16.f16.f32 "
        "{%0,%1,%2,%3}, {%4,%5,%6,%7}, {%8,%9}, {%0,%1,%2,%3};"
        : "+f"(d[0]), "+f"(d[1]), "+f"(d[2]), "+f"(d[3])
        : "r"(a[0]), "r"(a[1]), "r"(a[2]), "r"(a[3]), "r"(b[0]), "r"(b[1]));
}

#define GBM 128
#define GBN 64
#define HSTRIDE 36   // uints per row (32 data + 4 pad)

template<bool IN_HALF, bool DO_SILU>
__global__ __launch_bounds__(256)
void gemm_tc(const void* __restrict__ Av, const float* __restrict__ W,
             const float* __restrict__ bias, __half* __restrict__ outh,
             int M, int N) {
    __shared__ unsigned As_h[GBM * HSTRIDE];
    __shared__ unsigned Ws_h[GBN * HSTRIDE];

    int tid  = threadIdx.x;
    int warp = tid >> 5, lane = tid & 31;
    int g = lane >> 2, t4 = lane & 3;
    int wm = warp >> 1, wn = warp & 1;
    int bm = blockIdx.y * GBM, bn = blockIdx.x * GBN;

    float acc[2][4][4];
    #pragma unroll
    for (int i = 0; i < 2; i++)
        #pragma unroll
        for (int j = 0; j < 4; j++)
            #pragma unroll
            for (int k = 0; k < 4; k++) acc[i][j][k] = 0.f;

    #pragma unroll
    for (int k0 = 0; k0 < 128; k0 += 64) {
        if (IN_HALF) {
            const uint2* A_h = reinterpret_cast<const uint2*>(Av);
            #pragma unroll
            for (int r = 0; r < 8; r++) {
                int t  = tid + r * 256;
                int ml = t >> 4, c = t & 15;
                uint2 v = make_uint2(0, 0);
                if (bm + ml < M) v = A_h[(size_t)(bm + ml) * 32 + k0 / 4 + c];
                *reinterpret_cast<uint2*>(As_h + ml * HSTRIDE + c * 2) = v;
            }
        } else {
            const float* A = reinterpret_cast<const float*>(Av);
            #pragma unroll
            for (int r = 0; r < 8; r++) {
                int t  = tid + r * 256;
                int ml = t >> 4, c = t & 15;
                float4 v = make_float4(0, 0, 0, 0);
                if (bm + ml < M) v = *reinterpret_cast<const float4*>(A + (size_t)(bm + ml) * 128 + k0 + c * 4);
                *reinterpret_cast<uint2*>(As_h + ml * HSTRIDE + c * 2) = f4toh4(v);
            }
        }
        #pragma unroll
        for (int r = 0; r < 4; r++) {
            int t  = tid + r * 256;
            int nl = t >> 4, c = t & 15;
            float4 v = *reinterpret_cast<const float4*>(W + (size_t)(bn + nl) * 128 + k0 + c * 4);
            *reinterpret_cast<uint2*>(Ws_h + nl * HSTRIDE + c * 2) = f4toh4(v);
        }
        __syncthreads();

        #pragma unroll
        for (int ks = 0; ks < 4; ks++) {
            int ku = ks * 8;
            unsigned a[2][4], b[4][2];
            #pragma unroll
            for (int tm = 0; tm < 2; tm++) {
                int mb = wm * 32 + tm * 16;
                const unsigned* r0 = As_h + (mb + g) * HSTRIDE + ku;
                const unsigned* r1 = As_h + (mb + 8 + g) * HSTRIDE + ku;
                a[tm][0] = r0[t4];     a[tm][1] = r1[t4];
                a[tm][2] = r0[t4 + 4]; a[tm][3] = r1[t4 + 4];
            }
            #pragma unroll
            for (int tn = 0; tn < 4; tn++) {
                int nb = wn * 32 + tn * 8;
                const unsigned* rw = Ws_h + (nb + g) * HSTRIDE + ku;
                b[tn][0] = rw[t4]; b[tn][1] = rw[t4 + 4];
            }
            #pragma unroll
            for (int tm = 0; tm < 2; tm++)
                #pragma unroll
                for (int tn = 0; tn < 4; tn++)
                    mma_f16(acc[tm][tn], a[tm], b[tn]);
        }
        __syncthreads();
    }

    #pragma unroll
    for (int tm = 0; tm < 2; tm++) {
        #pragma unroll
        for (int tn = 0; tn < 4; tn++) {
            int row0 = bm + wm * 32 + tm * 16 + g;
            int col  = bn + wn * 32 + tn * 8 + t4 * 2;
            float b0 = __ldg(bias + col), b1 = __ldg(bias + col + 1);
            float v0 = acc[tm][tn][0] + b0;
            float v1 = acc[tm][tn][1] + b1;
            float v2 = acc[tm][tn][2] + b0;
            float v3 = acc[tm][tn][3] + b1;
            if (DO_SILU) {
                v0 = v0 / (1.0f + __expf(-v0));
                v1 = v1 / (1.0f + __expf(-v1));
                v2 = v2 / (1.0f + __expf(-v2));
                v3 = v3 / (1.0f + __expf(-v3));
            }
            __half2 h01 = __floats2half2_rn(v0, v1);
            __half2 h23 = __floats2half2_rn(v2, v3);
            if (row0 < M)
                *reinterpret_cast<__half2*>(outh + (size_t)row0 * N + col) = h01;
            if (row0 + 8 < M)
                *reinterpret_cast<__half2*>(outh + (size_t)(row0 + 8) * N + col) = h23;
        }
    }
}

// ---------------- aggregation: asymmetric pipeline + L2 hints ---------------
// Wij (read-once DRAM stream) -> cp.async ring depth 4, L2::evict_first.
// x/mu (reused 77MB working set) -> register ping-pong, L2 evict_last policy.
#define WDEPTH 4
#define MAXSEG 64
#define AGG_SMEM (24576 + 1024 + 1024 + 4096)

struct XM {
    uint2 x0, x1, x2, m0, m1, m2;
    float d0, d1, d2;
};

__global__ __launch_bounds__(128)
void k_agg(const float* __restrict__ q, const float* __restrict__ mu,
           const float* __restrict__ Wij, const float* __restrict__ dir,
           const int* __restrict__ idxj, float* __restrict__ out) {
    extern __shared__ char dsm[];
    int warp = threadIdx.x >> 5;
    int lane = threadIdx.x & 31;

    float4* sw = reinterpret_cast<float4*>(dsm)              + warp * (WDEPTH * 96);
    int*    sp = reinterpret_cast<int*>(dsm + 24576)         + warp * MAXSEG;
    int*    sj = reinterpret_cast<int*>(dsm + 24576 + 1024)  + warp * MAXSEG;
    float4* sd = reinterpret_cast<float4*>(dsm + 24576 + 2048) + warp * MAXSEG;

    int i = blockIdx.x * 4 + warp;
    if (i >= N_ATOMS) return;

    unsigned long long polEF = mk_evict_first();
    unsigned long long polEL = mk_evict_last();

    int s = g_offset[i], e = g_offset[i + 1];
    int n = e - s;

    int nc = n < MAXSEG ? n : MAXSEG;
    for (int t = lane; t < nc; t += 32) {
        int p = __ldg(g_pairidx + s + t);
        sp[t] = p;
        sj[t] = __ldg(idxj + p);
        sd[t] = make_float4(__ldg(dir + (size_t)p * 3 + 0),
                            __ldg(dir + (size_t)p * 3 + 1),
                            __ldg(dir + (size_t)p * 3 + 2), 0.f);
    }
    __syncwarp();

    float4 aq = make_float4(0, 0, 0, 0);
    float4 a0 = aq, a1 = aq, a2 = aq;

    auto issue_w = [&](int t) {
        if (t < n) {
            int p = (t < MAXSEG) ? sp[t] : __ldg(g_pairidx + s + t);
            int slot = t & (WDEPTH - 1);
            const char* wsrc = (const char*)Wij + (size_t)p * 1536 + lane * 16;
            unsigned wdst = smem_u32(sw + slot * 96 + lane);
            cp16_ef(wdst,        wsrc,        polEF);
            cp16_ef(wdst + 512,  wsrc + 512,  polEF);
            cp16_ef(wdst + 1024, wsrc + 1024, polEF);
        }
        cp_commit();
    };

    auto load_xm = [&](XM& R, int t) {
        int p, j;
        if (t < MAXSEG) {
            j = sj[t];
            float4 dv = sd[t];
            R.d0 = dv.x; R.d1 = dv.y; R.d2 = dv.z;
        } else {
            p = __ldg(g_pairidx + s + t);
            j = __ldg(idxj + p);
            R.d0 = __ldg(dir + (size_t)p * 3 + 0);
            R.d1 = __ldg(dir + (size_t)p * 3 + 1);
            R.d2 = __ldg(dir + (size_t)p * 3 + 2);
        }
        const uint2* xp = reinterpret_cast<const uint2*>(g_xh)  + (size_t)j * 96;
        const uint2* mp = reinterpret_cast<const uint2*>(g_muh) + (size_t)j * 96;
        R.x0 = ldg_el(xp + lane, polEL);
        R.x1 = ldg_el(xp + lane + 32, polEL);
        R.x2 = ldg_el(xp + lane + 64, polEL);
        R.m0 = ldg_el(mp + lane, polEL);
        R.m1 = ldg_el(mp + lane + 32, polEL);
        R.m2 = ldg_el(mp + lane + 64, polEL);
    };

    auto accum = [&](const XM& R, int slot) {
        float4 w0 = sw[slot * 96 + lane];
        float4 w1 = sw[slot * 96 + lane + 32];
        float4 w2 = sw[slot * 96 + lane + 64];
        float4 x0 = h4tof4(R.x0), x1 = h4tof4(R.x1), x2 = h4tof4(R.x2);
        float4 m0 = h4tof4(R.m0), m1 = h4tof4(R.m1), m2 = h4tof4(R.m2);
        aq = f4fma(w0, x0, aq);
        float4 Rv = f4mul(w1, x1);
        float4 MM = f4mul(w2, x2);
        a0 = f4fma(MM, m0, f4fmas(Rv, R.d0, a0));
        a1 = f4fma(MM, m1, f4fmas(Rv, R.d1, a1));
        a2 = f4fma(MM, m2, f4fmas(Rv, R.d2, a2));
    };

    XM A, B;
    issue_w(0); issue_w(1); issue_w(2);
    if (n > 0) load_xm(A, 0);

    for (int t = 0; t < n; ) {
        issue_w(t + 3);
        if (t + 1 < n) load_xm(B, t + 1);
        cp_wait<WDEPTH - 1>();
        accum(A, t & (WDEPTH - 1));
        ++t;
        if (t >= n) break;

        issue_w(t + 3);
        if (t + 1 < n) load_xm(A, t + 1);
        cp_wait<WDEPTH - 1>();
        accum(B, t & (WDEPTH - 1));
        ++t;
    }

    const float4* qp = reinterpret_cast<const float4*>(q) + (size_t)i * 32;
    float4* oq = reinterpret_cast<float4*>(out) + (size_t)i * 32;
    oq[lane] = f4add(qp[lane], aq);

    const float4* mup = reinterpret_cast<const float4*>(mu) + (size_t)i * 96;
    float4* om = reinterpret_cast<float4*>(out + (size_t)N_ATOMS * FDIM) + (size_t)i * 96;
    om[lane]      = f4add(mup[lane],      a0);
    om[lane + 32] = f4add(mup[lane + 32], a1);
    om[lane + 64] = f4add(mup[lane + 64], a2);
}

// ---------------- launch ----------------------------------------------------
static cudaStream_t s_side = nullptr;
static cudaEvent_t  s_evFork = nullptr, s_evJoin = nullptr;

extern "C" void kernel_launch(void* const* d_in, const int* in_sizes, int n_in,
                              void* d_out, int out_size) {
    const float* q   = (const float*)d_in[0];
    const float* mu  = (const float*)d_in[1];
    const float* Wij = (const float*)d_in[2];
    const float* dir = (const float*)d_in[3];
    const int*   pl  = (const int*)d_in[4];
    const float* W1  = (const float*)d_in[5];
    const float* b1  = (const float*)d_in[6];
    const float* W2  = (const float*)d_in[7];
    const float* b2  = (const float*)d_in[8];
    float* out = (float*)d_out;

    const int* idx_i = pl;
    const int* idx_j = pl + N_PAIRS;

    __half *hbuf = nullptr, *xh = nullptr;
    cudaGetSymbolAddress((void**)&hbuf, g_h);
    cudaGetSymbolAddress((void**)&xh,   g_xh);

    if (!s_side) {
        cudaStreamCreateWithFlags(&s_side, cudaStreamNonBlocking);
        cudaEventCreateWithFlags(&s_evFork, cudaEventDisableTiming);
        cudaEventCreateWithFlags(&s_evJoin, cudaEventDisableTiming);
        cudaFuncSetAttribute(k_agg, cudaFuncAttributeMaxDynamicSharedMemorySize, AGG_SMEM);
    }

    // fork: CSR chain + mu conversion on side stream, GEMM chain on main
    cudaEventRecord(s_evFork, 0);
    cudaStreamWaitEvent(s_side, s_evFork, 0);

    k_zero   <<<(N_ATOMS + 255) / 256, 256, 0, s_side>>>();
    k_hist   <<<(N_PAIRS + 255) / 256, 256, 0, s_side>>>(idx_i);
    k_scan   <<<1, 1024, 0, s_side>>>();
    k_scatter<<<(N_PAIRS + 255) / 256, 256, 0, s_side>>>(idx_i);
    {
        size_t n4 = (size_t)N_ATOMS * F3 / 4;
        k_cvt_mu<<<(unsigned)((n4 + 255) / 256), 256, 0, s_side>>>(mu);
    }
    cudaEventRecord(s_evJoin, s_side);

    // main: fp16 tensor-core GEMM chain
    dim3 g1(FDIM / GBN, (N_ATOMS + GBM - 1) / GBM);
    gemm_tc<false, true><<<g1, 256>>>(q, W1, b1, hbuf, N_ATOMS, FDIM);
    dim3 g2(F3 / GBN, (N_ATOMS + GBM - 1) / GBM);
    gemm_tc<true, false><<<g2, 256>>>(hbuf, W2, b2, xh, N_ATOMS, F3);

    // join, then aggregate
    cudaStreamWaitEvent(0, s_evJoin, 0);
    k_agg<<<(N_ATOMS + 3) / 4, 128, AGG_SMEM>>>(q, mu, Wij, dir, idx_j, out);
}

// round 14
// speedup vs baseline: 1.3797x; 1.0772x over previous
#include <cuda_runtime.h>
#include <cuda_fp16.h>

#define N_ATOMS 50000
#define N_PAIRS 800000
#define FDIM    128
#define F3      384

// ---------------- scratch (device globals; no runtime allocation) ----------
__device__ int    g_count [N_ATOMS];
__device__ int    g_cursor[N_ATOMS];
__device__ int    g_offset[N_ATOMS + 1];
__device__ int    g_pairidx[N_PAIRS];
__device__ __half g_h  [(size_t)N_ATOMS * FDIM];  // 12.8 MB (h in fp16)
__device__ __half g_xh [(size_t)N_ATOMS * F3];    // 38.4 MB (x in fp16)
__device__ __half g_muh[(size_t)N_ATOMS * F3];    // 38.4 MB (mu in fp16)

// ---------------- small float4 helpers -------------------------------------
__device__ __forceinline__ float4 f4add(float4 a, float4 b) {
    return make_float4(a.x + b.x, a.y + b.y, a.z + b.z, a.w + b.w);
}
__device__ __forceinline__ float4 f4mul(float4 a, float4 b) {
    return make_float4(a.x * b.x, a.y * b.y, a.z * b.z, a.w * b.w);
}
__device__ __forceinline__ float4 f4fma(float4 a, float4 b, float4 c) {
    return make_float4(fmaf(a.x, b.x, c.x), fmaf(a.y, b.y, c.y),
                       fmaf(a.z, b.z, c.z), fmaf(a.w, b.w, c.w));
}
__device__ __forceinline__ float4 f4fmas(float4 a, float s, float4 c) {
    return make_float4(fmaf(a.x, s, c.x), fmaf(a.y, s, c.y),
                       fmaf(a.z, s, c.z), fmaf(a.w, s, c.w));
}
__device__ __forceinline__ float4 h4tof4(uint2 u) {
    __half2 a = *reinterpret_cast<__half2*>(&u.x);
    __half2 b = *reinterpret_cast<__half2*>(&u.y);
    float2 fa = __half22float2(a), fb = __half22float2(b);
    return make_float4(fa.x, fa.y, fb.x, fb.y);
}
__device__ __forceinline__ uint2 f4toh4(float4 v) {
    __half2 h0 = __floats2half2_rn(v.x, v.y);
    __half2 h1 = __floats2half2_rn(v.z, v.w);
    uint2 u;
    u.x = *reinterpret_cast<unsigned*>(&h0);
    u.y = *reinterpret_cast<unsigned*>(&h1);
    return u;
}

// ---------------- cp.async / cache-policy helpers ---------------------------
__device__ __forceinline__ unsigned smem_u32(const void* p) {
    return (unsigned)__cvta_generic_to_shared(p);
}
__device__ __forceinline__ unsigned long long mk_evict_first() {
    unsigned long long pol;
    asm("createpolicy.fractional.L2::evict_first.b64 %0, 1.0;" : "=l"(pol));
    return pol;
}
__device__ __forceinline__ unsigned long long mk_evict_last() {
    unsigned long long pol;
    asm("createpolicy.fractional.L2::evict_last.b64 %0, 1.0;" : "=l"(pol));
    return pol;
}
__device__ __forceinline__ void cp16_ef(unsigned d, const void* s, unsigned long long pol) {
    asm volatile("cp.async.cg.shared.global.L2::cache_hint [%0], [%1], 16, %2;"
                 :: "r"(d), "l"(s), "l"(pol));
}
__device__ __forceinline__ void cp_commit() {
    asm volatile("cp.async.commit_group;");
}
template<int N> __device__ __forceinline__ void cp_wait() {
    asm volatile("cp.async.wait_group %0;" :: "n"(N));
}
// x/mu gathers: keep in L2 via cache-policy operand form
__device__ __forceinline__ uint2 ldg_el(const uint2* p, unsigned long long pol) {
    uint2 v;
    asm volatile("ld.global.nc.L2::cache_hint.v2.u32 {%0,%1}, [%2], %3;"
                 : "=r"(v.x), "=r"(v.y) : "l"(p), "l"(pol));
    return v;
}
// out stores: evict_first (written once, never read) -> don't pollute L2
__device__ __forceinline__ void stg_ef(float4* p, float4 v, unsigned long long pol) {
    asm volatile("st.global.L2::cache_hint.v4.f32 [%0], {%1,%2,%3,%4}, %5;"
                 :: "l"(p), "f"(v.x), "f"(v.y), "f"(v.z), "f"(v.w), "l"(pol));
}

// ---------------- CSR build -------------------------------------------------
__global__ void k_zero() {
    int i = blockIdx.x * blockDim.x + threadIdx.x;
    if (i < N_ATOMS) { g_count[i] = 0; g_cursor[i] = 0; }
}

__global__ void k_hist(const int* __restrict__ idx_i) {
    int p = blockIdx.x * blockDim.x + threadIdx.x;
    if (p < N_PAIRS) atomicAdd(&g_count[idx_i[p]], 1);
}

__global__ void k_scan() {
    __shared__ int warpsum[33];
    int lane = threadIdx.x & 31, wid = threadIdx.x >> 5;
    int running = 0;
    for (int base = 0; base < N_ATOMS; base += 1024) {
        int idx = base + (int)threadIdx.x;
        int v = (idx < N_ATOMS) ? g_count[idx] : 0;
        int incl = v;
        #pragma unroll
        for (int off = 1; off < 32; off <<= 1) {
            int t = __shfl_up_sync(0xffffffff, incl, off);
            if (lane >= off) incl += t;
        }
        if (lane == 31) warpsum[wid] = incl;
        __syncthreads();
        if (wid == 0) {
            int s = warpsum[lane];
            int si = s;
            #pragma unroll
            for (int off = 1; off < 32; off <<= 1) {
                int t = __shfl_up_sync(0xffffffff, si, off);
                if (lane >= off) si += t;
            }
            warpsum[lane] = si - s;
            if (lane == 31) warpsum[32] = si;
        }
        __syncthreads();
        if (idx < N_ATOMS) g_offset[idx] = running + warpsum[wid] + incl - v;
        running += warpsum[32];
        __syncthreads();
    }
    if (threadIdx.x == 0) g_offset[N_ATOMS] = running;
}

__global__ void k_scatter(const int* __restrict__ idx_i) {
    int p = blockIdx.x * blockDim.x + threadIdx.x;
    if (p < N_PAIRS) {
        int i = idx_i[p];
        int pos = atomicAdd(&g_cursor[i], 1);
        g_pairidx[g_offset[i] + pos] = p;
    }
}

// ---------------- mu -> fp16 mirror ----------------------------------------
__global__ void k_cvt_mu(const float* __restrict__ mu) {
    size_t i = (size_t)blockIdx.x * blockDim.x + threadIdx.x;
    size_t n4 = (size_t)N_ATOMS * F3 / 4;
    if (i >= n4) return;
    reinterpret_cast<uint2*>(g_muh)[i] = f4toh4(reinterpret_cast<const float4*>(mu)[i]);
}

// ---------------- fp16 tensor-core GEMM (m16n8k16, fp32 accum) -------------
__device__ __forceinline__ void mma_f16(float* d, const unsigned* a, const unsigned* b) {
    asm volatile(
        "mma.sync.aligned.m16n8k16.row.col.f32.f16.f16.f32 "
        "{%0,%1,%2,%3}, {%4,%5,%6,%7}, {%8,%9}, {%0,%1,%2,%3};"
        : "+f"(d[0]), "+f"(d[1]), "+f"(d[2]), "+f"(d[3])
        : "r"(a[0]), "r"(a[1]), "r"(a[2]), "r"(a[3]), "r"(b[0]), "r"(b[1]));
}

#define GBM 128
#define GBN 64
#define HSTRIDE 36   // uints per row (32 data + 4 pad)

template<bool IN_HALF, bool DO_SILU>
__global__ __launch_bounds__(256)
void gemm_tc(const void* __restrict__ Av, const float* __restrict__ W,
             const float* __restrict__ bias, __half* __restrict__ outh,
             int M, int N) {
    __shared__ unsigned As_h[GBM * HSTRIDE];
    __shared__ unsigned Ws_h[GBN * HSTRIDE];

    int tid  = threadIdx.x;
    int warp = tid >> 5, lane = tid & 31;
    int g = lane >> 2, t4 = lane & 3;
    int wm = warp >> 1, wn = warp & 1;
    int bm = blockIdx.y * GBM, bn = blockIdx.x * GBN;

    float acc[2][4][4];
    #pragma unroll
    for (int i = 0; i < 2; i++)
        #pragma unroll
        for (int j = 0; j < 4; j++)
            #pragma unroll
            for (int k = 0; k < 4; k++) acc[i][j][k] = 0.f;

    #pragma unroll
    for (int k0 = 0; k0 < 128; k0 += 64) {
        if (IN_HALF) {
            const uint2* A_h = reinterpret_cast<const uint2*>(Av);
            #pragma unroll
            for (int r = 0; r < 8; r++) {
                int t  = tid + r * 256;
                int ml = t >> 4, c = t & 15;
                uint2 v = make_uint2(0, 0);
                if (bm + ml < M) v = A_h[(size_t)(bm + ml) * 32 + k0 / 4 + c];
                *reinterpret_cast<uint2*>(As_h + ml * HSTRIDE + c * 2) = v;
            }
        } else {
            const float* A = reinterpret_cast<const float*>(Av);
            #pragma unroll
            for (int r = 0; r < 8; r++) {
                int t  = tid + r * 256;
                int ml = t >> 4, c = t & 15;
                float4 v = make_float4(0, 0, 0, 0);
                if (bm + ml < M) v = *reinterpret_cast<const float4*>(A + (size_t)(bm + ml) * 128 + k0 + c * 4);
                *reinterpret_cast<uint2*>(As_h + ml * HSTRIDE + c * 2) = f4toh4(v);
            }
        }
        #pragma unroll
        for (int r = 0; r < 4; r++) {
            int t  = tid + r * 256;
            int nl = t >> 4, c = t & 15;
            float4 v = *reinterpret_cast<const float4*>(W + (size_t)(bn + nl) * 128 + k0 + c * 4);
            *reinterpret_cast<uint2*>(Ws_h + nl * HSTRIDE + c * 2) = f4toh4(v);
        }
        __syncthreads();

        #pragma unroll
        for (int ks = 0; ks < 4; ks++) {
            int ku = ks * 8;
            unsigned a[2][4], b[4][2];
            #pragma unroll
            for (int tm = 0; tm < 2; tm++) {
                int mb = wm * 32 + tm * 16;
                const unsigned* r0 = As_h + (mb + g) * HSTRIDE + ku;
                const unsigned* r1 = As_h + (mb + 8 + g) * HSTRIDE + ku;
                a[tm][0] = r0[t4];     a[tm][1] = r1[t4];
                a[tm][2] = r0[t4 + 4]; a[tm][3] = r1[t4 + 4];
            }
            #pragma unroll
            for (int tn = 0; tn < 4; tn++) {
                int nb = wn * 32 + tn * 8;
                const unsigned* rw = Ws_h + (nb + g) * HSTRIDE + ku;
                b[tn][0] = rw[t4]; b[tn][1] = rw[t4 + 4];
            }
            #pragma unroll
            for (int tm = 0; tm < 2; tm++)
                #pragma unroll
                for (int tn = 0; tn < 4; tn++)
                    mma_f16(acc[tm][tn], a[tm], b[tn]);
        }
        __syncthreads();
    }

    #pragma unroll
    for (int tm = 0; tm < 2; tm++) {
        #pragma unroll
        for (int tn = 0; tn < 4; tn++) {
            int row0 = bm + wm * 32 + tm * 16 + g;
            int col  = bn + wn * 32 + tn * 8 + t4 * 2;
            float b0 = __ldg(bias + col), b1 = __ldg(bias + col + 1);
            float v0 = acc[tm][tn][0] + b0;
            float v1 = acc[tm][tn][1] + b1;
            float v2 = acc[tm][tn][2] + b0;
            float v3 = acc[tm][tn][3] + b1;
            if (DO_SILU) {
                v0 = v0 / (1.0f + __expf(-v0));
                v1 = v1 / (1.0f + __expf(-v1));
                v2 = v2 / (1.0f + __expf(-v2));
                v3 = v3 / (1.0f + __expf(-v3));
            }
            __half2 h01 = __floats2half2_rn(v0, v1);
            __half2 h23 = __floats2half2_rn(v2, v3);
            if (row0 < M)
                *reinterpret_cast<__half2*>(outh + (size_t)row0 * N + col) = h01;
            if (row0 + 8 < M)
                *reinterpret_cast<__half2*>(outh + (size_t)(row0 + 8) * N + col) = h23;
        }
    }
}

// ---------------- aggregation: asymmetric pipeline + L2 hints ---------------
// Wij (read-once DRAM stream) -> cp.async ring depth 4, L2::evict_first.
// x/mu (reused 77MB working set) -> register ping-pong, L2 evict_last policy.
// out stores -> evict_first (write-once).
#define WDEPTH 4
#define MAXSEG 32
#define AGG_SMEM (24576 + 512 + 512 + 2048)

struct XM {
    uint2 x0, x1, x2, m0, m1, m2;
    float d0, d1, d2;
};

__global__ __launch_bounds__(128)
void k_agg(const float* __restrict__ q, const float* __restrict__ mu,
           const float* __restrict__ Wij, const float* __restrict__ dir,
           const int* __restrict__ idxj, float* __restrict__ out) {
    extern __shared__ char dsm[];
    int warp = threadIdx.x >> 5;
    int lane = threadIdx.x & 31;

    float4* sw = reinterpret_cast<float4*>(dsm)              + warp * (WDEPTH * 96);
    int*    sp = reinterpret_cast<int*>(dsm + 24576)         + warp * MAXSEG;
    int*    sj = reinterpret_cast<int*>(dsm + 24576 + 512)   + warp * MAXSEG;
    float4* sd = reinterpret_cast<float4*>(dsm + 24576 + 1024) + warp * MAXSEG;

    int i = blockIdx.x * 4 + warp;
    if (i >= N_ATOMS) return;

    unsigned long long polEF = mk_evict_first();
    unsigned long long polEL = mk_evict_last();

    int s = g_offset[i], e = g_offset[i + 1];
    int n = e - s;

    int nc = n < MAXSEG ? n : MAXSEG;
    for (int t = lane; t < nc; t += 32) {
        int p = __ldg(g_pairidx + s + t);
        sp[t] = p;
        sj[t] = __ldg(idxj + p);
        sd[t] = make_float4(__ldg(dir + (size_t)p * 3 + 0),
                            __ldg(dir + (size_t)p * 3 + 1),
                            __ldg(dir + (size_t)p * 3 + 2), 0.f);
    }
    __syncwarp();

    float4 aq = make_float4(0, 0, 0, 0);
    float4 a0 = aq, a1 = aq, a2 = aq;

    auto issue_w = [&](int t) {
        if (t < n) {
            int p = (t < MAXSEG) ? sp[t] : __ldg(g_pairidx + s + t);
            int slot = t & (WDEPTH - 1);
            const char* wsrc = (const char*)Wij + (size_t)p * 1536 + lane * 16;
            unsigned wdst = smem_u32(sw + slot * 96 + lane);
            cp16_ef(wdst,        wsrc,        polEF);
            cp16_ef(wdst + 512,  wsrc + 512,  polEF);
            cp16_ef(wdst + 1024, wsrc + 1024, polEF);
        }
        cp_commit();
    };

    auto load_xm = [&](XM& R, int t) {
        int p, j;
        if (t < MAXSEG) {
            j = sj[t];
            float4 dv = sd[t];
            R.d0 = dv.x; R.d1 = dv.y; R.d2 = dv.z;
        } else {
            p = __ldg(g_pairidx + s + t);
            j = __ldg(idxj + p);
            R.d0 = __ldg(dir + (size_t)p * 3 + 0);
            R.d1 = __ldg(dir + (size_t)p * 3 + 1);
            R.d2 = __ldg(dir + (size_t)p * 3 + 2);
        }
        const uint2* xp = reinterpret_cast<const uint2*>(g_xh)  + (size_t)j * 96;
        const uint2* mp = reinterpret_cast<const uint2*>(g_muh) + (size_t)j * 96;
        R.x0 = ldg_el(xp + lane, polEL);
        R.x1 = ldg_el(xp + lane + 32, polEL);
        R.x2 = ldg_el(xp + lane + 64, polEL);
        R.m0 = ldg_el(mp + lane, polEL);
        R.m1 = ldg_el(mp + lane + 32, polEL);
        R.m2 = ldg_el(mp + lane + 64, polEL);
    };

    auto accum = [&](const XM& R, int slot) {
        float4 w0 = sw[slot * 96 + lane];
        float4 w1 = sw[slot * 96 + lane + 32];
        float4 w2 = sw[slot * 96 + lane + 64];
        float4 x0 = h4tof4(R.x0), x1 = h4tof4(R.x1), x2 = h4tof4(R.x2);
        float4 m0 = h4tof4(R.m0), m1 = h4tof4(R.m1), m2 = h4tof4(R.m2);
        aq = f4fma(w0, x0, aq);
        float4 Rv = f4mul(w1, x1);
        float4 MM = f4mul(w2, x2);
        a0 = f4fma(MM, m0, f4fmas(Rv, R.d0, a0));
        a1 = f4fma(MM, m1, f4fmas(Rv, R.d1, a1));
        a2 = f4fma(MM, m2, f4fmas(Rv, R.d2, a2));
    };

    XM A, B;
    issue_w(0); issue_w(1); issue_w(2);
    if (n > 0) load_xm(A, 0);

    for (int t = 0; t < n; ) {
        issue_w(t + 3);
        if (t + 1 < n) load_xm(B, t + 1);
        cp_wait<WDEPTH - 1>();
        accum(A, t & (WDEPTH - 1));
        ++t;
        if (t >= n) break;

        issue_w(t + 3);
        if (t + 1 < n) load_xm(A, t + 1);
        cp_wait<WDEPTH - 1>();
        accum(B, t & (WDEPTH - 1));
        ++t;
    }

    const float4* qp = reinterpret_cast<const float4*>(q) + (size_t)i * 32;
    float4* oq = reinterpret_cast<float4*>(out) + (size_t)i * 32;
    stg_ef(oq + lane, f4add(qp[lane], aq), polEF);

    const float4* mup = reinterpret_cast<const float4*>(mu) + (size_t)i * 96;
    float4* om = reinterpret_cast<float4*>(out + (size_t)N_ATOMS * FDIM) + (size_t)i * 96;
    stg_ef(om + lane,      f4add(mup[lane],      a0), polEF);
    stg_ef(om + lane + 32, f4add(mup[lane + 32], a1), polEF);
    stg_ef(om + lane + 64, f4add(mup[lane + 64], a2), polEF);
}

// ---------------- launch ----------------------------------------------------
static cudaStream_t s_side = nullptr;
static cudaEvent_t  s_evFork = nullptr, s_evJoin = nullptr;

extern "C" void kernel_launch(void* const* d_in, const int* in_sizes, int n_in,
                              void* d_out, int out_size) {
    const float* q   = (const float*)d_in[0];
    const float* mu  = (const float*)d_in[1];
    const float* Wij = (const float*)d_in[2];
    const float* dir = (const float*)d_in[3];
    const int*   pl  = (const int*)d_in[4];
    const float* W1  = (const float*)d_in[5];
    const float* b1  = (const float*)d_in[6];
    const float* W2  = (const float*)d_in[7];
    const float* b2  = (const float*)d_in[8];
    float* out = (float*)d_out;

    const int* idx_i = pl;
    const int* idx_j = pl + N_PAIRS;

    __half *hbuf = nullptr, *xh = nullptr;
    cudaGetSymbolAddress((void**)&hbuf, g_h);
    cudaGetSymbolAddress((void**)&xh,   g_xh);

    if (!s_side) {
        cudaStreamCreateWithFlags(&s_side, cudaStreamNonBlocking);
        cudaEventCreateWithFlags(&s_evFork, cudaEventDisableTiming);
        cudaEventCreateWithFlags(&s_evJoin, cudaEventDisableTiming);
        cudaFuncSetAttribute(k_agg, cudaFuncAttributeMaxDynamicSharedMemorySize, AGG_SMEM);
    }

    // fork: CSR chain on side stream; cvt_mu + GEMM chain on main (balanced)
    cudaEventRecord(s_evFork, 0);
    cudaStreamWaitEvent(s_side, s_evFork, 0);

    k_zero   <<<(N_ATOMS + 255) / 256, 256, 0, s_side>>>();
    k_hist   <<<(N_PAIRS + 255) / 256, 256, 0, s_side>>>(idx_i);
    k_scan   <<<1, 1024, 0, s_side>>>();
    k_scatter<<<(N_PAIRS + 255) / 256, 256, 0, s_side>>>(idx_i);
    cudaEventRecord(s_evJoin, s_side);

    {
        size_t n4 = (size_t)N_ATOMS * F3 / 4;
        k_cvt_mu<<<(unsigned)((n4 + 255) / 256), 256>>>(mu);
    }
    dim3 g1(FDIM / GBN, (N_ATOMS + GBM - 1) / GBM);
    gemm_tc<false, true><<<g1, 256>>>(q, W1, b1, hbuf, N_ATOMS, FDIM);
    dim3 g2(F3 / GBN, (N_ATOMS + GBM - 1) / GBM);
    gemm_tc<true, false><<<g2, 256>>>(hbuf, W2, b2, xh, N_ATOMS, F3);

    // join, then aggregate
    cudaStreamWaitEvent(0, s_evJoin, 0);
    k_agg<<<(N_ATOMS + 3) / 4, 128, AGG_SMEM>>>(q, mu, Wij, dir, idx_j, out);
}